// round 11
// baseline (speedup 1.0000x reference)
#include <cuda_runtime.h>
#include <cuda_bf16.h>
#include <stdint.h>

#define BHN 16
#define LEN 2048
#define DIM 64
#define RN  4
#define NB2 16
#define CH  128
#define NK  256
#define SSTR 160   // k_scores row stride in bf16 (320B; %128B alternates 0/64)
#define VS2  544   // k_av vT row stride in bf16 (1088B; %128B alternates 0/64)

typedef unsigned long long ull;

// ---------------- scratch (device globals; allocation-free) ----------------
__device__ float  g_qn  [BHN][LEN][DIM];
__device__ float  g_rmn [BHN][DIM][64];
__device__ int    g_hash[BHN][RN][LEN];
__device__ int    g_hidx[BHN][RN][LEN];
__device__ int    g_oidx[BHN][RN][LEN];
__device__ float  g_sc  [BHN][RN][LEN][NK];  // adjusted scores, then p (in-place)
__device__ float  g_attn[BHN][RN][LEN][DIM];

__constant__ float c_log4[4] = {0.0f, 0.6931471805599453f, 1.0986122886681098f, 1.3862943611198906f};

// fast exp on the FMA pipe — R2's exact version
__device__ __forceinline__ float fexp(float x) {
    x = fmaxf(x, -87.0f);
    float t = fmaf(x, 1.4426950408889634f, 12582912.0f);
    int n = __float_as_int(t) - 0x4B400000;
    float fi = t - 12582912.0f;
    float z = fmaf(fi, -0.6931471805599453f, x);
    float p = 8.3333337e-3f;
    p = fmaf(p, z, 4.1666668e-2f);
    p = fmaf(p, z, 0.16666667f);
    p = fmaf(p, z, 0.5f);
    p = fmaf(p, z, 1.0f);
    p = fmaf(p, z, 1.0f);
    return p * __int_as_float((n + 127) << 23);
}

// ---------------- mma.sync bf16 m16n8k16 ----------------
__device__ __forceinline__ void mma_bf16(float* c, const uint32_t* a, uint32_t b0, uint32_t b1) {
    asm volatile(
        "mma.sync.aligned.m16n8k16.row.col.f32.bf16.bf16.f32 "
        "{%0,%1,%2,%3}, {%4,%5,%6,%7}, {%8,%9}, {%0,%1,%2,%3};"
        : "+f"(c[0]), "+f"(c[1]), "+f"(c[2]), "+f"(c[3])
        : "r"(a[0]), "r"(a[1]), "r"(a[2]), "r"(a[3]), "r"(b0), "r"(b1));
}

// split float2 -> packed bf16 hi (x) and lo (y); low half = .x
__device__ __forceinline__ uint2 split2(float2 f) {
    __nv_bfloat16 h0 = __float2bfloat16(f.x);
    __nv_bfloat16 h1 = __float2bfloat16(f.y);
    __nv_bfloat16 l0 = __float2bfloat16(f.x - __bfloat162float(h0));
    __nv_bfloat16 l1 = __float2bfloat16(f.y - __bfloat162float(h1));
    uint2 r;
    r.x = ((uint32_t)__bfloat16_as_ushort(h1) << 16) | __bfloat16_as_ushort(h0);
    r.y = ((uint32_t)__bfloat16_as_ushort(l1) << 16) | __bfloat16_as_ushort(l0);
    return r;
}

// ---------------- K0: normalize rand_matrix columns ----------------
__global__ void k_rmn(const float* __restrict__ rm) {
    int b = blockIdx.x;
    int j = threadIdx.x;
    float s = 0.f;
    for (int d = 0; d < DIM; d++) {
        float v = rm[(size_t)(b * DIM + d) * 64 + j];
        s += v * v;
    }
    float inv = rsqrtf(s);
    for (int d = 0; d < DIM; d++)
        g_rmn[b][d][j] = rm[(size_t)(b * DIM + d) * 64 + j] * inv;
}

// ---------------- K1: normalize q + hashes ----------------
__global__ void __launch_bounds__(128) k_hash(const float* __restrict__ q) {
    int b = blockIdx.y;
    __shared__ float s_rm[DIM * 64];
    int tid = threadIdx.x;
    const float4* rsrc = (const float4*)&g_rmn[b][0][0];
    for (int t = tid; t < DIM * 64 / 4; t += 128) ((float4*)s_rm)[t] = rsrc[t];
    __syncthreads();

    int l = blockIdx.x * 128 + tid;
    float qv[DIM];
    const float4* qp = (const float4*)&q[((size_t)b * LEN + l) * DIM];
#pragma unroll
    for (int t = 0; t < 16; t++) {
        float4 v = qp[t];
        qv[4 * t] = v.x; qv[4 * t + 1] = v.y; qv[4 * t + 2] = v.z; qv[4 * t + 3] = v.w;
    }
    float ss = 0.f;
#pragma unroll
    for (int d = 0; d < DIM; d++) ss += qv[d] * qv[d];
    float inv = rsqrtf(ss);
#pragma unroll
    for (int d = 0; d < DIM; d++) qv[d] *= inv;
    float4* qd = (float4*)&g_qn[b][l][0];
#pragma unroll
    for (int t = 0; t < 16; t++)
        qd[t] = make_float4(qv[4 * t], qv[4 * t + 1], qv[4 * t + 2], qv[4 * t + 3]);

    for (int r = 0; r < RN; r++) {
        float bp = -1e30f, bn = -1e30f;
        int bpi = 0, bni = 0;
        for (int k = 0; k < 16; k++) {
            float acc = 0.f;
#pragma unroll
            for (int d = 0; d < DIM; d++) acc += qv[d] * s_rm[d * 64 + r * 16 + k];
            if (acc > bp)  { bp = acc;  bpi = k; }
            if (-acc > bn) { bn = -acc; bni = k; }
        }
        g_hash[b][r][l] = (bn > bp) ? (16 + bni) : bpi;
    }
}

// ---------------- K2: stable counting sort per (b,r) ----------------
__global__ void __launch_bounds__(256) k_sort() {
    int b = blockIdx.x >> 2, r = blockIdx.x & 3;
    __shared__ int hist[32][257];
    __shared__ int base[32];
    int t = threadIdx.x;
#pragma unroll
    for (int v = 0; v < 32; v++) hist[v][t] = 0;
    __syncthreads();
    int h[8];
#pragma unroll
    for (int e = 0; e < 8; e++) {
        h[e] = g_hash[b][r][t * 8 + e];
        hist[h[e]][t]++;
    }
    __syncthreads();
    if (t < 32) {
        int run = 0;
        for (int i = 0; i < 256; i++) { int x = hist[t][i]; hist[t][i] = run; run += x; }
        base[t] = run;
    }
    __syncthreads();
    if (t == 0) {
        int run = 0;
        for (int v = 0; v < 32; v++) { int x = base[v]; base[v] = run; run += x; }
    }
    __syncthreads();
#pragma unroll
    for (int e = 0; e < 8; e++) {
        int l = t * 8 + e, v = h[e];
        int off = hist[v][t];
        hist[v][t] = off + 1;
        int pos = base[v] + off;
        g_hidx[b][r][pos] = l;
        g_oidx[b][r][l] = pos;
    }
}

// ---------------- K3: bf16-split mma.sync score GEMM, fragment-native layout ----------------
// smem: kmeta int2[256] @0, xs @4096: 256 rows x SSTR bf16 (interleaved h/l fragment slots)
#define SM3_TOTAL (4096 + NK * SSTR * 2)

__global__ void __launch_bounds__(512) k_scores() {
    int n = blockIdx.x, r = blockIdx.y, b = blockIdx.z;
    extern __shared__ char sm3[];
    int2* kmeta = (int2*)sm3;   // .x = (khash<<16)|kidx, .y = packed chunk per round
    __nv_bfloat16* xs = (__nv_bfloat16*)(sm3 + 4096);
    int tid = threadIdx.x;
    int prevbase = ((n + NB2 - 1) & (NB2 - 1)) * CH;

    for (int j = tid; j < NK; j += 512) {
        int keypos = (j < CH) ? (prevbase + j) : (n * CH + j - CH);
        int ki = g_hidx[b][r][keypos];
        int kh = g_hash[b][r][ki];
        int pc = 0;
#pragma unroll
        for (int rr = 0; rr < RN; rr++)
            pc |= ((g_oidx[b][rr][ki] >> 7) & 15) << (8 * rr);
        kmeta[j] = make_int2((kh << 16) | ki, pc);
    }
    __syncthreads();

    // stage: slot (row, chunk c, t4s) = 16B {h(k0),h(k0+1) | h(k0+8),h(k0+9) | l k0-pair | l k0+8-pair}
    for (int t = tid; t < NK * 16; t += 512) {
        int row = t >> 4;
        int c   = (t >> 2) & 3;
        int t4s = t & 3;
        int k0 = c * 16 + 2 * t4s;
        int ki = kmeta[row].x & 0xFFFF;
        const float* src = &g_qn[b][ki][0];
        uint2 sa = split2(*(const float2*)&src[k0]);
        uint2 sb = split2(*(const float2*)&src[k0 + 8]);
        *(uint4*)&xs[row * SSTR + c * 32 + t4s * 8] = make_uint4(sa.x, sb.x, sa.y, sb.y);
    }
    __syncthreads();

    int wid = tid >> 5, lane = tid & 31;
    int wm = wid >> 1, wn = wid & 1;
    int i0 = wm * 16, j0 = wn * 128;
    int g = lane >> 2, t4 = lane & 3;

    float acc[16][4];
#pragma unroll
    for (int nt = 0; nt < 16; nt++)
#pragma unroll
        for (int c = 0; c < 4; c++) acc[nt][c] = 0.f;

#pragma unroll
    for (int ks = 0; ks < 4; ks++) {
        int coff = ks * 32 + t4 * 8;
        uint4 a0 = *(const uint4*)&xs[(CH + i0 + g) * SSTR + coff];
        uint4 a1 = *(const uint4*)&xs[(CH + i0 + g + 8) * SSTR + coff];
        uint32_t ah[4] = {a0.x, a1.x, a0.y, a1.y};
        uint32_t al[4] = {a0.z, a1.z, a0.w, a1.w};
#pragma unroll
        for (int nt = 0; nt < 16; nt++) {
            uint4 bb = *(const uint4*)&xs[(j0 + nt * 8 + g) * SSTR + coff];
            mma_bf16(acc[nt], ah, bb.x, bb.y);
            mma_bf16(acc[nt], ah, bb.z, bb.w);
            mma_bf16(acc[nt], al, bb.x, bb.y);
        }
    }

    int ia = i0 + g, ib = i0 + g + 8;
    int2 qa = kmeta[CH + ia], qb = kmeta[CH + ib];
    int qidxa = qa.x & 0xFFFF, qha = qa.x >> 16, npa = qa.y;
    int qidxb = qb.x & 0xFFFF, qhb = qb.x >> 16, npb = qb.y;
    int ppa = ((npa | 0x10101010) - 0x01010101) & 0x0f0f0f0f;
    int ppb = ((npb | 0x10101010) - 0x01010101) & 0x0f0f0f0f;
    float* rowa = &g_sc[b][r][n * CH + ia][0];
    float* rowb = &g_sc[b][r][n * CH + ib][0];
#pragma unroll
    for (int nt = 0; nt < 16; nt++) {
        int j = j0 + nt * 8 + 2 * t4;
        int4 km = *(const int4*)&kmeta[j];
        int kj0 = km.x & 0xFFFF, kh0 = km.x >> 16, kc0 = km.y;
        int kj1 = km.z & 0xFFFF, kh1 = km.z >> 16, kc1 = km.w;
        float o00 = acc[nt][0] * 0.125f, o01 = acc[nt][1] * 0.125f;
        float o10 = acc[nt][2] * 0.125f, o11 = acc[nt][3] * 0.125f;
        if (qidxa == kj0)                      o00 = -100000.0f;
        else if (qidxa < kj0 || qha != kh0)    o00 = -1000000000.0f;
        if (qidxa == kj1)                      o01 = -100000.0f;
        else if (qidxa < kj1 || qha != kh1)    o01 = -1000000000.0f;
        if (qidxb == kj0)                      o10 = -100000.0f;
        else if (qidxb < kj0 || qhb != kh0)    o10 = -1000000000.0f;
        if (qidxb == kj1)                      o11 = -100000.0f;
        else if (qidxb < kj1 || qhb != kh1)    o11 = -1000000000.0f;
        unsigned m;
        m = __vcmpeq4((unsigned)kc0, (unsigned)npa) | __vcmpeq4((unsigned)kc0, (unsigned)ppa);
        o00 -= c_log4[(__popc(m) >> 3) - 1];
        m = __vcmpeq4((unsigned)kc1, (unsigned)npa) | __vcmpeq4((unsigned)kc1, (unsigned)ppa);
        o01 -= c_log4[(__popc(m) >> 3) - 1];
        m = __vcmpeq4((unsigned)kc0, (unsigned)npb) | __vcmpeq4((unsigned)kc0, (unsigned)ppb);
        o10 -= c_log4[(__popc(m) >> 3) - 1];
        m = __vcmpeq4((unsigned)kc1, (unsigned)npb) | __vcmpeq4((unsigned)kc1, (unsigned)ppb);
        o11 -= c_log4[(__popc(m) >> 3) - 1];
        *(float2*)&rowa[j] = make_float2(o00, o01);
        *(float2*)&rowb[j] = make_float2(o10, o11);
    }
}

// ---------------- K4: joint softmax (in-place, float4 lanes) ----------------
__global__ void __launch_bounds__(512) k_softmax() {
    int b = blockIdx.y;
    int warp = threadIdx.x >> 5, lane = threadIdx.x & 31;
#pragma unroll 1
    for (int it = 0; it < 16; it++) {
        int l = blockIdx.x * 256 + it * 16 + warp;
        int srs[RN];
        float4 adj[RN][2];
        float mx = -3.4e38f;
#pragma unroll
        for (int r = 0; r < RN; r++) {
            srs[r] = g_oidx[b][r][l];
            const float4* srow = (const float4*)&g_sc[b][r][srs[r]][0];
            adj[r][0] = srow[lane];
            adj[r][1] = srow[lane + 32];
#pragma unroll
            for (int h = 0; h < 2; h++) {
                mx = fmaxf(mx, fmaxf(fmaxf(adj[r][h].x, adj[r][h].y),
                                     fmaxf(adj[r][h].z, adj[r][h].w)));
            }
        }
#pragma unroll
        for (int o = 16; o; o >>= 1) mx = fmaxf(mx, __shfl_xor_sync(0xffffffffu, mx, o));
        float sum = 0.f;
#pragma unroll
        for (int r = 0; r < RN; r++)
#pragma unroll
            for (int h = 0; h < 2; h++) {
                adj[r][h].x = fexp(adj[r][h].x - mx);
                adj[r][h].y = fexp(adj[r][h].y - mx);
                adj[r][h].z = fexp(adj[r][h].z - mx);
                adj[r][h].w = fexp(adj[r][h].w - mx);
                sum += adj[r][h].x + adj[r][h].y + adj[r][h].z + adj[r][h].w;
            }
#pragma unroll
        for (int o = 16; o; o >>= 1) sum += __shfl_xor_sync(0xffffffffu, sum, o);
        float inv = 1.0f / sum;
#pragma unroll
        for (int r = 0; r < RN; r++) {
            float4* srow = (float4*)&g_sc[b][r][srs[r]][0];
#pragma unroll
            for (int h = 0; h < 2; h++) {
                float4 w = adj[r][h];
                w.x *= inv; w.y *= inv; w.z *= inv; w.w *= inv;
                srow[lane + h * 32] = w;
            }
        }
    }
}

// ---------------- K5: bf16-split mma.sync p @ v_sorted, fragment-native vT ----------------
#define SM5_TOTAL (64 * VS2 * 2)

__global__ void __launch_bounds__(512) k_av(const float* __restrict__ v) {
    int n = blockIdx.x, r = blockIdx.y, b = blockIdx.z;
    extern __shared__ char sm5[];
    __nv_bfloat16* vs = (__nv_bfloat16*)sm5;   // 64 rows (d) x VS2 bf16
    int tid = threadIdx.x;
    int prevbase = ((n + NB2 - 1) & (NB2 - 1)) * CH;

    // stage vT in fragment-native slots: for j-pair (ja even), h-pair at
    // d*VS2*2B + c*64 + t4s*16 + half*4, l-pair at +8
    for (int idx = tid; idx < 128 * 16; idx += 512) {
        int jp = idx & 127, f = idx >> 7;
        int ja = 2 * jp, jb = ja + 1;
        int kpa = (ja < CH) ? (prevbase + ja) : (n * CH + ja - CH);
        int kpb = (jb < CH) ? (prevbase + jb) : (n * CH + jb - CH);
        int kia = g_hidx[b][r][kpa];
        int kib = g_hidx[b][r][kpb];
        float4 va = *(const float4*)&v[((size_t)b * LEN + kia) * DIM + f * 4];
        float4 vb = *(const float4*)&v[((size_t)b * LEN + kib) * DIM + f * 4];
        float pa[4] = {va.x, va.y, va.z, va.w};
        float pb[4] = {vb.x, vb.y, vb.z, vb.w};
        int c  = ja >> 4;
        int p  = (ja & 15) >> 1;
        int boff = c * 64 + (p & 3) * 16 + (p >> 2) * 4;
#pragma unroll
        for (int cc = 0; cc < 4; cc++) {
            uint2 s = split2(make_float2(pa[cc], pb[cc]));
            char* base = (char*)vs + (f * 4 + cc) * (VS2 * 2) + boff;
            *(uint32_t*)base = s.x;
            *(uint32_t*)(base + 8) = s.y;
        }
    }
    __syncthreads();

    int wid = tid >> 5, lane = tid & 31;
    int wm = wid >> 1, wn = wid & 1;
    int i0 = wm * 16, d0 = wn * 32;
    int g = lane >> 2, t4 = lane & 3;

    float acc[4][4];
#pragma unroll
    for (int nt = 0; nt < 4; nt++)
#pragma unroll
        for (int c = 0; c < 4; c++) acc[nt][c] = 0.f;

    const float* pA0 = &g_sc[b][r][n * CH + i0 + g][0];
    const float* pA8 = &g_sc[b][r][n * CH + i0 + g + 8][0];
#pragma unroll 4
    for (int ks = 0; ks < 16; ks++) {
        int k0 = ks * 16 + 2 * t4;
        uint2 s0 = split2(*(const float2*)&pA0[k0]);
        uint2 s1 = split2(*(const float2*)&pA8[k0]);
        uint2 s2 = split2(*(const float2*)&pA0[k0 + 8]);
        uint2 s3 = split2(*(const float2*)&pA8[k0 + 8]);
        uint32_t ah[4] = {s0.x, s1.x, s2.x, s3.x};
        uint32_t al[4] = {s0.y, s1.y, s2.y, s3.y};
        int coff = ks * 32 + t4 * 8;
#pragma unroll
        for (int nt = 0; nt < 4; nt++) {
            uint4 bb = *(const uint4*)&vs[(d0 + nt * 8 + g) * VS2 + coff];
            mma_bf16(acc[nt], ah, bb.x, bb.y);
            mma_bf16(acc[nt], ah, bb.z, bb.w);
            mma_bf16(acc[nt], al, bb.x, bb.y);
        }
    }

    int ia = i0 + g, ib = ia + 8;
#pragma unroll
    for (int nt = 0; nt < 4; nt++) {
        int d = d0 + nt * 8 + 2 * t4;
        *(float2*)&g_attn[b][r][n * CH + ia][d] = make_float2(acc[nt][0], acc[nt][1]);
        *(float2*)&g_attn[b][r][n * CH + ib][d] = make_float2(acc[nt][2], acc[nt][3]);
    }
}

// ---------------- K6: gather rounds back to original order, sum ----------------
__global__ void __launch_bounds__(256) k_out(float* __restrict__ out) {
    int gid = blockIdx.x * 256 + threadIdx.x;
    int dq = gid & 15;
    int l = (gid >> 4) & (LEN - 1);
    int b = gid >> 15;
    float4 s = make_float4(0.f, 0.f, 0.f, 0.f);
#pragma unroll
    for (int r = 0; r < RN; r++) {
        int sIdx = g_oidx[b][r][l];
        float4 a = *(const float4*)&g_attn[b][r][sIdx][dq * 4];
        s.x += a.x; s.y += a.y; s.z += a.z; s.w += a.w;
    }
    *(float4*)&out[((size_t)b * LEN + l) * DIM + dq * 4] = s;
}

// ---------------- launch ----------------
extern "C" void kernel_launch(void* const* d_in, const int* in_sizes, int n_in,
                              void* d_out, int out_size) {
    const float* q  = (const float*)d_in[0];
    const float* v  = (const float*)d_in[1];
    const float* rm = (const float*)d_in[2];
    float* out = (float*)d_out;

    cudaFuncSetAttribute(k_scores, cudaFuncAttributeMaxDynamicSharedMemorySize, SM3_TOTAL);
    cudaFuncSetAttribute(k_av,     cudaFuncAttributeMaxDynamicSharedMemorySize, SM5_TOTAL);

    k_rmn<<<BHN, 64>>>(rm);
    k_hash<<<dim3(LEN / 128, BHN), 128>>>(q);
    k_sort<<<BHN * RN, 256>>>();
    k_scores<<<dim3(NB2, RN, BHN), 512, SM3_TOTAL>>>();   // launch #3 -> ncu slot
    k_softmax<<<dim3(LEN / 256, BHN), 512>>>();
    k_av<<<dim3(NB2, RN, BHN), 512, SM5_TOTAL>>>(v);
    k_out<<<(BHN * LEN * 16) / 256, 256>>>(out);
}

// round 12
// speedup vs baseline: 1.0576x; 1.0576x over previous
#include <cuda_runtime.h>
#include <cuda_bf16.h>
#include <stdint.h>

#define BHN 16
#define LEN 2048
#define DIM 64
#define RN  4
#define NB2 16
#define CH  128
#define NK  256
#define XSTR 72    // k_scores staged row stride (bf16)
#define VSTR 264   // k_av vT row stride (bf16)

typedef unsigned long long ull;

// ---------------- scratch (device globals; allocation-free) ----------------
__device__ float    g_qn  [BHN][LEN][DIM];
__device__ float    g_rmn [BHN][DIM][64];
__device__ int      g_hash[BHN][RN][LEN];
__device__ int      g_hidx[BHN][RN][LEN];
__device__ int      g_oidx[BHN][RN][LEN];
__device__ float    g_sc  [BHN][RN][LEN][NK];   // adjusted scores (read-only after K3)
__device__ uint32_t g_pb  [BHN][RN][LEN][NK];   // p packed bf16: pair p -> {hi,lo} at [2p],[2p+1]
__device__ float    g_attn[BHN][RN][LEN][DIM];

__constant__ float c_log4[4] = {0.0f, 0.6931471805599453f, 1.0986122886681098f, 1.3862943611198906f};

// fast exp on the FMA pipe — R2's exact version
__device__ __forceinline__ float fexp(float x) {
    x = fmaxf(x, -87.0f);
    float t = fmaf(x, 1.4426950408889634f, 12582912.0f);
    int n = __float_as_int(t) - 0x4B400000;
    float fi = t - 12582912.0f;
    float z = fmaf(fi, -0.6931471805599453f, x);
    float p = 8.3333337e-3f;
    p = fmaf(p, z, 4.1666668e-2f);
    p = fmaf(p, z, 0.16666667f);
    p = fmaf(p, z, 0.5f);
    p = fmaf(p, z, 1.0f);
    p = fmaf(p, z, 1.0f);
    return p * __int_as_float((n + 127) << 23);
}

// ---------------- mma.sync bf16 m16n8k16 ----------------
__device__ __forceinline__ void mma_bf16(float* c, const uint32_t* a, uint32_t b0, uint32_t b1) {
    asm volatile(
        "mma.sync.aligned.m16n8k16.row.col.f32.bf16.bf16.f32 "
        "{%0,%1,%2,%3}, {%4,%5,%6,%7}, {%8,%9}, {%0,%1,%2,%3};"
        : "+f"(c[0]), "+f"(c[1]), "+f"(c[2]), "+f"(c[3])
        : "r"(a[0]), "r"(a[1]), "r"(a[2]), "r"(a[3]), "r"(b0), "r"(b1));
}

// split float2 -> packed bf16 hi (x) and lo (y); low half = .x
__device__ __forceinline__ uint2 split2(float2 f) {
    __nv_bfloat16 h0 = __float2bfloat16(f.x);
    __nv_bfloat16 h1 = __float2bfloat16(f.y);
    __nv_bfloat16 l0 = __float2bfloat16(f.x - __bfloat162float(h0));
    __nv_bfloat16 l1 = __float2bfloat16(f.y - __bfloat162float(h1));
    uint2 r;
    r.x = ((uint32_t)__bfloat16_as_ushort(h1) << 16) | __bfloat16_as_ushort(h0);
    r.y = ((uint32_t)__bfloat16_as_ushort(l1) << 16) | __bfloat16_as_ushort(l0);
    return r;
}

// ---------------- K0: normalize rand_matrix columns ----------------
__global__ void k_rmn(const float* __restrict__ rm) {
    int b = blockIdx.x;
    int j = threadIdx.x;
    float s = 0.f;
    for (int d = 0; d < DIM; d++) {
        float v = rm[(size_t)(b * DIM + d) * 64 + j];
        s += v * v;
    }
    float inv = rsqrtf(s);
    for (int d = 0; d < DIM; d++)
        g_rmn[b][d][j] = rm[(size_t)(b * DIM + d) * 64 + j] * inv;
}

// ---------------- K1: normalize q + hashes ----------------
__global__ void __launch_bounds__(128) k_hash(const float* __restrict__ q) {
    int b = blockIdx.y;
    __shared__ float s_rm[DIM * 64];
    int tid = threadIdx.x;
    const float4* rsrc = (const float4*)&g_rmn[b][0][0];
    for (int t = tid; t < DIM * 64 / 4; t += 128) ((float4*)s_rm)[t] = rsrc[t];
    __syncthreads();

    int l = blockIdx.x * 128 + tid;
    float qv[DIM];
    const float4* qp = (const float4*)&q[((size_t)b * LEN + l) * DIM];
#pragma unroll
    for (int t = 0; t < 16; t++) {
        float4 v = qp[t];
        qv[4 * t] = v.x; qv[4 * t + 1] = v.y; qv[4 * t + 2] = v.z; qv[4 * t + 3] = v.w;
    }
    float ss = 0.f;
#pragma unroll
    for (int d = 0; d < DIM; d++) ss += qv[d] * qv[d];
    float inv = rsqrtf(ss);
#pragma unroll
    for (int d = 0; d < DIM; d++) qv[d] *= inv;
    float4* qd = (float4*)&g_qn[b][l][0];
#pragma unroll
    for (int t = 0; t < 16; t++)
        qd[t] = make_float4(qv[4 * t], qv[4 * t + 1], qv[4 * t + 2], qv[4 * t + 3]);

    for (int r = 0; r < RN; r++) {
        float bp = -1e30f, bn = -1e30f;
        int bpi = 0, bni = 0;
        for (int k = 0; k < 16; k++) {
            float acc = 0.f;
#pragma unroll
            for (int d = 0; d < DIM; d++) acc += qv[d] * s_rm[d * 64 + r * 16 + k];
            if (acc > bp)  { bp = acc;  bpi = k; }
            if (-acc > bn) { bn = -acc; bni = k; }
        }
        g_hash[b][r][l] = (bn > bp) ? (16 + bni) : bpi;
    }
}

// ---------------- K2: stable counting sort per (b,r) ----------------
__global__ void __launch_bounds__(256) k_sort() {
    int b = blockIdx.x >> 2, r = blockIdx.x & 3;
    __shared__ int hist[32][257];
    __shared__ int base[32];
    int t = threadIdx.x;
#pragma unroll
    for (int v = 0; v < 32; v++) hist[v][t] = 0;
    __syncthreads();
    int h[8];
#pragma unroll
    for (int e = 0; e < 8; e++) {
        h[e] = g_hash[b][r][t * 8 + e];
        hist[h[e]][t]++;
    }
    __syncthreads();
    if (t < 32) {
        int run = 0;
        for (int i = 0; i < 256; i++) { int x = hist[t][i]; hist[t][i] = run; run += x; }
        base[t] = run;
    }
    __syncthreads();
    if (t == 0) {
        int run = 0;
        for (int v = 0; v < 32; v++) { int x = base[v]; base[v] = run; run += x; }
    }
    __syncthreads();
#pragma unroll
    for (int e = 0; e < 8; e++) {
        int l = t * 8 + e, v = h[e];
        int off = hist[v][t];
        hist[v][t] = off + 1;
        int pos = base[v] + off;
        g_hidx[b][r][pos] = l;
        g_oidx[b][r][l] = pos;
    }
}

// ---------------- K3: bf16-split mma.sync score GEMM (R10 verbatim) ----------------
#define SM3_TOTAL (4096 + 2 * NK * XSTR * 2)

__global__ void __launch_bounds__(512) k_scores() {
    int n = blockIdx.x, r = blockIdx.y, b = blockIdx.z;
    extern __shared__ char sm3[];
    int2* kmeta = (int2*)sm3;   // .x = (khash<<16)|kidx, .y = packed chunk per round
    __nv_bfloat16* xh = (__nv_bfloat16*)(sm3 + 4096);
    __nv_bfloat16* xl = (__nv_bfloat16*)(sm3 + 4096 + NK * XSTR * 2);
    int tid = threadIdx.x;
    int prevbase = ((n + NB2 - 1) & (NB2 - 1)) * CH;

    for (int j = tid; j < NK; j += 512) {
        int keypos = (j < CH) ? (prevbase + j) : (n * CH + j - CH);
        int ki = g_hidx[b][r][keypos];
        int kh = g_hash[b][r][ki];
        int pc = 0;
#pragma unroll
        for (int rr = 0; rr < RN; rr++)
            pc |= ((g_oidx[b][rr][ki] >> 7) & 15) << (8 * rr);
        kmeta[j] = make_int2((kh << 16) | ki, pc);
    }
    __syncthreads();

    for (int t = tid; t < NK * 16; t += 512) {
        int row = t >> 4, cg = t & 15;
        int ki = kmeta[row].x & 0xFFFF;
        float4 v = *(const float4*)&g_qn[b][ki][cg * 4];
        uint2 p0 = split2(make_float2(v.x, v.y));
        uint2 p1 = split2(make_float2(v.z, v.w));
        *(uint2*)&xh[row * XSTR + cg * 4] = make_uint2(p0.x, p1.x);
        *(uint2*)&xl[row * XSTR + cg * 4] = make_uint2(p0.y, p1.y);
    }
    __syncthreads();

    int wid = tid >> 5, lane = tid & 31;
    int wm = wid >> 1, wn = wid & 1;
    int i0 = wm * 16, j0 = wn * 128;
    int g = lane >> 2, t4 = lane & 3;

    float acc[16][4];
#pragma unroll
    for (int nt = 0; nt < 16; nt++)
#pragma unroll
        for (int c = 0; c < 4; c++) acc[nt][c] = 0.f;

    const __nv_bfloat16* Ah = xh + (CH + i0) * XSTR;
    const __nv_bfloat16* Al = xl + (CH + i0) * XSTR;
#pragma unroll
    for (int ks = 0; ks < 4; ks++) {
        int k0 = ks * 16 + 2 * t4;
        uint32_t ah[4], al[4];
        ah[0] = *(const uint32_t*)&Ah[g * XSTR + k0];
        ah[1] = *(const uint32_t*)&Ah[(g + 8) * XSTR + k0];
        ah[2] = *(const uint32_t*)&Ah[g * XSTR + k0 + 8];
        ah[3] = *(const uint32_t*)&Ah[(g + 8) * XSTR + k0 + 8];
        al[0] = *(const uint32_t*)&Al[g * XSTR + k0];
        al[1] = *(const uint32_t*)&Al[(g + 8) * XSTR + k0];
        al[2] = *(const uint32_t*)&Al[g * XSTR + k0 + 8];
        al[3] = *(const uint32_t*)&Al[(g + 8) * XSTR + k0 + 8];
#pragma unroll
        for (int nt = 0; nt < 16; nt++) {
            int rowb = (j0 + nt * 8 + g) * XSTR + k0;
            uint32_t bh0 = *(const uint32_t*)&xh[rowb];
            uint32_t bh1 = *(const uint32_t*)&xh[rowb + 8];
            uint32_t bl0 = *(const uint32_t*)&xl[rowb];
            uint32_t bl1 = *(const uint32_t*)&xl[rowb + 8];
            mma_bf16(acc[nt], ah, bh0, bh1);
            mma_bf16(acc[nt], ah, bl0, bl1);
            mma_bf16(acc[nt], al, bh0, bh1);
        }
    }

    int ia = i0 + g, ib = i0 + g + 8;
    int2 qa = kmeta[CH + ia], qb = kmeta[CH + ib];
    int qidxa = qa.x & 0xFFFF, qha = qa.x >> 16, npa = qa.y;
    int qidxb = qb.x & 0xFFFF, qhb = qb.x >> 16, npb = qb.y;
    int ppa = ((npa | 0x10101010) - 0x01010101) & 0x0f0f0f0f;
    int ppb = ((npb | 0x10101010) - 0x01010101) & 0x0f0f0f0f;
    float* rowa = &g_sc[b][r][n * CH + ia][0];
    float* rowb = &g_sc[b][r][n * CH + ib][0];
#pragma unroll
    for (int nt = 0; nt < 16; nt++) {
        int j = j0 + nt * 8 + 2 * t4;          // even -> int4 aligned
        int4 km = *(const int4*)&kmeta[j];
        int kj0 = km.x & 0xFFFF, kh0 = km.x >> 16, kc0 = km.y;
        int kj1 = km.z & 0xFFFF, kh1 = km.z >> 16, kc1 = km.w;
        float o00 = acc[nt][0] * 0.125f, o01 = acc[nt][1] * 0.125f;
        float o10 = acc[nt][2] * 0.125f, o11 = acc[nt][3] * 0.125f;
        if (qidxa == kj0)                      o00 = -100000.0f;
        else if (qidxa < kj0 || qha != kh0)    o00 = -1000000000.0f;
        if (qidxa == kj1)                      o01 = -100000.0f;
        else if (qidxa < kj1 || qha != kh1)    o01 = -1000000000.0f;
        if (qidxb == kj0)                      o10 = -100000.0f;
        else if (qidxb < kj0 || qhb != kh0)    o10 = -1000000000.0f;
        if (qidxb == kj1)                      o11 = -100000.0f;
        else if (qidxb < kj1 || qhb != kh1)    o11 = -1000000000.0f;
        unsigned m;
        m = __vcmpeq4((unsigned)kc0, (unsigned)npa) | __vcmpeq4((unsigned)kc0, (unsigned)ppa);
        o00 -= c_log4[(__popc(m) >> 3) - 1];
        m = __vcmpeq4((unsigned)kc1, (unsigned)npa) | __vcmpeq4((unsigned)kc1, (unsigned)ppa);
        o01 -= c_log4[(__popc(m) >> 3) - 1];
        m = __vcmpeq4((unsigned)kc0, (unsigned)npb) | __vcmpeq4((unsigned)kc0, (unsigned)ppb);
        o10 -= c_log4[(__popc(m) >> 3) - 1];
        m = __vcmpeq4((unsigned)kc1, (unsigned)npb) | __vcmpeq4((unsigned)kc1, (unsigned)ppb);
        o11 -= c_log4[(__popc(m) >> 3) - 1];
        *(float2*)&rowa[j] = make_float2(o00, o01);
        *(float2*)&rowb[j] = make_float2(o10, o11);
    }
}

// ---------------- K4: joint softmax -> packed bf16-split p (g_pb) ----------------
__global__ void __launch_bounds__(512) k_softmax() {
    int b = blockIdx.y;
    int warp = threadIdx.x >> 5, lane = threadIdx.x & 31;
#pragma unroll 1
    for (int it = 0; it < 16; it++) {
        int l = blockIdx.x * 256 + it * 16 + warp;
        int srs[RN];
        float4 adj[RN][2];
        float mx = -3.4e38f;
#pragma unroll
        for (int r = 0; r < RN; r++) {
            srs[r] = g_oidx[b][r][l];
            const float4* srow = (const float4*)&g_sc[b][r][srs[r]][0];
            adj[r][0] = srow[lane];
            adj[r][1] = srow[lane + 32];
#pragma unroll
            for (int h = 0; h < 2; h++) {
                mx = fmaxf(mx, fmaxf(fmaxf(adj[r][h].x, adj[r][h].y),
                                     fmaxf(adj[r][h].z, adj[r][h].w)));
            }
        }
#pragma unroll
        for (int o = 16; o; o >>= 1) mx = fmaxf(mx, __shfl_xor_sync(0xffffffffu, mx, o));
        float sum = 0.f;
#pragma unroll
        for (int r = 0; r < RN; r++)
#pragma unroll
            for (int h = 0; h < 2; h++) {
                adj[r][h].x = fexp(adj[r][h].x - mx);
                adj[r][h].y = fexp(adj[r][h].y - mx);
                adj[r][h].z = fexp(adj[r][h].z - mx);
                adj[r][h].w = fexp(adj[r][h].w - mx);
                sum += adj[r][h].x + adj[r][h].y + adj[r][h].z + adj[r][h].w;
            }
#pragma unroll
        for (int o = 16; o; o >>= 1) sum += __shfl_xor_sync(0xffffffffu, sum, o);
        float inv = 1.0f / sum;
#pragma unroll
        for (int r = 0; r < RN; r++) {
            uint32_t* prow = &g_pb[b][r][srs[r]][0];
#pragma unroll
            for (int h = 0; h < 2; h++) {
                float4 w = adj[r][h];
                w.x *= inv; w.y *= inv; w.z *= inv; w.w *= inv;
                uint2 s0 = split2(make_float2(w.x, w.y));   // pair 2L(+64h)
                uint2 s1 = split2(make_float2(w.z, w.w));   // pair 2L+1(+64h)
                *(uint4*)&prow[h * 128 + 4 * lane] = make_uint4(s0.x, s0.y, s1.x, s1.y);
            }
        }
    }
}

// ---------------- K5: mma.sync p @ v_sorted, p fragments pre-split in g_pb ----------------
#define SM5_TOTAL (2 * 64 * VSTR * 2)

__global__ void __launch_bounds__(512) k_av(const float* __restrict__ v) {
    int n = blockIdx.x, r = blockIdx.y, b = blockIdx.z;
    extern __shared__ char sm5[];
    __nv_bfloat16* vh = (__nv_bfloat16*)sm5;
    __nv_bfloat16* vl = vh + 64 * VSTR;
    int tid = threadIdx.x;
    int prevbase = ((n + NB2 - 1) & (NB2 - 1)) * CH;

    for (int idx = tid; idx < 128 * 16; idx += 512) {
        int jp = idx & 127, f = idx >> 7;
        int ja = 2 * jp, jb = 2 * jp + 1;
        int kpa = (ja < CH) ? (prevbase + ja) : (n * CH + ja - CH);
        int kpb = (jb < CH) ? (prevbase + jb) : (n * CH + jb - CH);
        int kia = g_hidx[b][r][kpa];
        int kib = g_hidx[b][r][kpb];
        float4 va = *(const float4*)&v[((size_t)b * LEN + kia) * DIM + f * 4];
        float4 vb = *(const float4*)&v[((size_t)b * LEN + kib) * DIM + f * 4];
        float pa[4] = {va.x, va.y, va.z, va.w};
        float pb[4] = {vb.x, vb.y, vb.z, vb.w};
#pragma unroll
        for (int c = 0; c < 4; c++) {
            uint2 s = split2(make_float2(pa[c], pb[c]));
            *(uint32_t*)&vh[(f * 4 + c) * VSTR + 2 * jp] = s.x;
            *(uint32_t*)&vl[(f * 4 + c) * VSTR + 2 * jp] = s.y;
        }
    }
    __syncthreads();

    int wid = tid >> 5, lane = tid & 31;
    int wm = wid >> 1, wn = wid & 1;
    int i0 = wm * 16, d0 = wn * 32;
    int g = lane >> 2, t4 = lane & 3;

    float acc[4][4];
#pragma unroll
    for (int nt = 0; nt < 4; nt++)
#pragma unroll
        for (int c = 0; c < 4; c++) acc[nt][c] = 0.f;

    const uint32_t* pb0 = &g_pb[b][r][n * CH + i0 + g][0];
    const uint32_t* pb8 = &g_pb[b][r][n * CH + i0 + g + 8][0];
#pragma unroll 4
    for (int ks = 0; ks < 16; ks++) {
        int pi = 2 * (ks * 8 + t4);                  // {hi,lo} of pair k0/2
        uint2 u0 = *(const uint2*)&pb0[pi];          // row g,  k0
        uint2 u1 = *(const uint2*)&pb8[pi];          // row g+8, k0
        uint2 u2 = *(const uint2*)&pb0[pi + 8];      // row g,  k0+8
        uint2 u3 = *(const uint2*)&pb8[pi + 8];      // row g+8, k0+8
        uint32_t ah[4] = {u0.x, u1.x, u2.x, u3.x};
        uint32_t al[4] = {u0.y, u1.y, u2.y, u3.y};
#pragma unroll
        for (int nt = 0; nt < 4; nt++) {
            int rowb = (d0 + nt * 8 + g) * VSTR + ks * 16;
            uint32_t bh0 = *(const uint32_t*)&vh[rowb + 2 * t4];
            uint32_t bh1 = *(const uint32_t*)&vh[rowb + 2 * t4 + 8];
            uint32_t bl0 = *(const uint32_t*)&vl[rowb + 2 * t4];
            uint32_t bl1 = *(const uint32_t*)&vl[rowb + 2 * t4 + 8];
            mma_bf16(acc[nt], ah, bh0, bh1);
            mma_bf16(acc[nt], ah, bl0, bl1);
            mma_bf16(acc[nt], al, bh0, bh1);
        }
    }

    int ia = i0 + g, ib = ia + 8;
#pragma unroll
    for (int nt = 0; nt < 4; nt++) {
        int d = d0 + nt * 8 + 2 * t4;
        *(float2*)&g_attn[b][r][n * CH + ia][d] = make_float2(acc[nt][0], acc[nt][1]);
        *(float2*)&g_attn[b][r][n * CH + ib][d] = make_float2(acc[nt][2], acc[nt][3]);
    }
}

// ---------------- K6: gather rounds back to original order, sum ----------------
__global__ void __launch_bounds__(256) k_out(float* __restrict__ out) {
    int gid = blockIdx.x * 256 + threadIdx.x;
    int dq = gid & 15;
    int l = (gid >> 4) & (LEN - 1);
    int b = gid >> 15;
    float4 s = make_float4(0.f, 0.f, 0.f, 0.f);
#pragma unroll
    for (int r = 0; r < RN; r++) {
        int sIdx = g_oidx[b][r][l];
        float4 a = *(const float4*)&g_attn[b][r][sIdx][dq * 4];
        s.x += a.x; s.y += a.y; s.z += a.z; s.w += a.w;
    }
    *(float4*)&out[((size_t)b * LEN + l) * DIM + dq * 4] = s;
}

// ---------------- launch ----------------
extern "C" void kernel_launch(void* const* d_in, const int* in_sizes, int n_in,
                              void* d_out, int out_size) {
    const float* q  = (const float*)d_in[0];
    const float* v  = (const float*)d_in[1];
    const float* rm = (const float*)d_in[2];
    float* out = (float*)d_out;

    cudaFuncSetAttribute(k_scores, cudaFuncAttributeMaxDynamicSharedMemorySize, SM3_TOTAL);
    cudaFuncSetAttribute(k_av,     cudaFuncAttributeMaxDynamicSharedMemorySize, SM5_TOTAL);

    k_rmn<<<BHN, 64>>>(rm);
    k_hash<<<dim3(LEN / 128, BHN), 128>>>(q);
    k_sort<<<BHN * RN, 256>>>();
    k_scores<<<dim3(NB2, RN, BHN), 512, SM3_TOTAL>>>();   // launch #3 -> ncu slot
    k_softmax<<<dim3(LEN / 256, BHN), 512>>>();
    k_av<<<dim3(NB2, RN, BHN), 512, SM5_TOTAL>>>(v);
    k_out<<<(BHN * LEN * 16) / 256, 256>>>(out);
}

// round 13
// speedup vs baseline: 1.0772x; 1.0185x over previous
#include <cuda_runtime.h>
#include <cuda_bf16.h>
#include <stdint.h>

#define BHN 16
#define LEN 2048
#define DIM 64
#define RN  4
#define NB2 16
#define CH  128
#define NK  256
#define XSTR 72    // k_scores staged row stride (bf16)
#define VSTR 264   // k_av vT row stride (bf16)

typedef unsigned long long ull;

// ---------------- scratch (device globals; allocation-free) ----------------
__device__ float    g_qn  [BHN][LEN][DIM];
__device__ float    g_rmn [BHN][DIM][64];
__device__ int      g_hash[BHN][RN][LEN];
__device__ int      g_hidx[BHN][RN][LEN];
__device__ int      g_oidx[BHN][RN][LEN];
__device__ float    g_sc  [BHN][RN][LEN][NK];   // adjusted scores (read-only after K3)
__device__ uint32_t g_pb  [BHN][RN][LEN][NK];   // p packed bf16: pair p -> {hi,lo} at [2p],[2p+1]
__device__ float    g_attn[BHN][RN][LEN][DIM];

__constant__ float c_log4[4] = {0.0f, 0.6931471805599453f, 1.0986122886681098f, 1.3862943611198906f};

// fast exp on the FMA pipe — R2's exact version
__device__ __forceinline__ float fexp(float x) {
    x = fmaxf(x, -87.0f);
    float t = fmaf(x, 1.4426950408889634f, 12582912.0f);
    int n = __float_as_int(t) - 0x4B400000;
    float fi = t - 12582912.0f;
    float z = fmaf(fi, -0.6931471805599453f, x);
    float p = 8.3333337e-3f;
    p = fmaf(p, z, 4.1666668e-2f);
    p = fmaf(p, z, 0.16666667f);
    p = fmaf(p, z, 0.5f);
    p = fmaf(p, z, 1.0f);
    p = fmaf(p, z, 1.0f);
    return p * __int_as_float((n + 127) << 23);
}

// ---------------- mma.sync bf16 m16n8k16 ----------------
__device__ __forceinline__ void mma_bf16(float* c, const uint32_t* a, uint32_t b0, uint32_t b1) {
    asm volatile(
        "mma.sync.aligned.m16n8k16.row.col.f32.bf16.bf16.f32 "
        "{%0,%1,%2,%3}, {%4,%5,%6,%7}, {%8,%9}, {%0,%1,%2,%3};"
        : "+f"(c[0]), "+f"(c[1]), "+f"(c[2]), "+f"(c[3])
        : "r"(a[0]), "r"(a[1]), "r"(a[2]), "r"(a[3]), "r"(b0), "r"(b1));
}

// split float2 -> packed bf16 hi (x) and lo (y); low half = .x
__device__ __forceinline__ uint2 split2(float2 f) {
    __nv_bfloat16 h0 = __float2bfloat16(f.x);
    __nv_bfloat16 h1 = __float2bfloat16(f.y);
    __nv_bfloat16 l0 = __float2bfloat16(f.x - __bfloat162float(h0));
    __nv_bfloat16 l1 = __float2bfloat16(f.y - __bfloat162float(h1));
    uint2 r;
    r.x = ((uint32_t)__bfloat16_as_ushort(h1) << 16) | __bfloat16_as_ushort(h0);
    r.y = ((uint32_t)__bfloat16_as_ushort(l1) << 16) | __bfloat16_as_ushort(l0);
    return r;
}

// ---------------- K0: normalize rand_matrix columns ----------------
__global__ void k_rmn(const float* __restrict__ rm) {
    int b = blockIdx.x;
    int j = threadIdx.x;
    float s = 0.f;
    for (int d = 0; d < DIM; d++) {
        float v = rm[(size_t)(b * DIM + d) * 64 + j];
        s += v * v;
    }
    float inv = rsqrtf(s);
    for (int d = 0; d < DIM; d++)
        g_rmn[b][d][j] = rm[(size_t)(b * DIM + d) * 64 + j] * inv;
}

// ---------------- K1: normalize q + hashes ----------------
__global__ void __launch_bounds__(128) k_hash(const float* __restrict__ q) {
    int b = blockIdx.y;
    __shared__ float s_rm[DIM * 64];
    int tid = threadIdx.x;
    const float4* rsrc = (const float4*)&g_rmn[b][0][0];
    for (int t = tid; t < DIM * 64 / 4; t += 128) ((float4*)s_rm)[t] = rsrc[t];
    __syncthreads();

    int l = blockIdx.x * 128 + tid;
    float qv[DIM];
    const float4* qp = (const float4*)&q[((size_t)b * LEN + l) * DIM];
#pragma unroll
    for (int t = 0; t < 16; t++) {
        float4 v = qp[t];
        qv[4 * t] = v.x; qv[4 * t + 1] = v.y; qv[4 * t + 2] = v.z; qv[4 * t + 3] = v.w;
    }
    float ss = 0.f;
#pragma unroll
    for (int d = 0; d < DIM; d++) ss += qv[d] * qv[d];
    float inv = rsqrtf(ss);
#pragma unroll
    for (int d = 0; d < DIM; d++) qv[d] *= inv;
    float4* qd = (float4*)&g_qn[b][l][0];
#pragma unroll
    for (int t = 0; t < 16; t++)
        qd[t] = make_float4(qv[4 * t], qv[4 * t + 1], qv[4 * t + 2], qv[4 * t + 3]);

    for (int r = 0; r < RN; r++) {
        float bp = -1e30f, bn = -1e30f;
        int bpi = 0, bni = 0;
        for (int k = 0; k < 16; k++) {
            float acc = 0.f;
#pragma unroll
            for (int d = 0; d < DIM; d++) acc += qv[d] * s_rm[d * 64 + r * 16 + k];
            if (acc > bp)  { bp = acc;  bpi = k; }
            if (-acc > bn) { bn = -acc; bni = k; }
        }
        g_hash[b][r][l] = (bn > bp) ? (16 + bni) : bpi;
    }
}

// ---------------- K2: stable counting sort per (b,r) ----------------
__global__ void __launch_bounds__(256) k_sort() {
    int b = blockIdx.x >> 2, r = blockIdx.x & 3;
    __shared__ int hist[32][257];
    __shared__ int base[32];
    int t = threadIdx.x;
#pragma unroll
    for (int v = 0; v < 32; v++) hist[v][t] = 0;
    __syncthreads();
    int h[8];
#pragma unroll
    for (int e = 0; e < 8; e++) {
        h[e] = g_hash[b][r][t * 8 + e];
        hist[h[e]][t]++;
    }
    __syncthreads();
    if (t < 32) {
        int run = 0;
        for (int i = 0; i < 256; i++) { int x = hist[t][i]; hist[t][i] = run; run += x; }
        base[t] = run;
    }
    __syncthreads();
    if (t == 0) {
        int run = 0;
        for (int v = 0; v < 32; v++) { int x = base[v]; base[v] = run; run += x; }
    }
    __syncthreads();
#pragma unroll
    for (int e = 0; e < 8; e++) {
        int l = t * 8 + e, v = h[e];
        int off = hist[v][t];
        hist[v][t] = off + 1;
        int pos = base[v] + off;
        g_hidx[b][r][pos] = l;
        g_oidx[b][r][l] = pos;
    }
}

// ---------------- K3: bf16-split mma.sync score GEMM, 1024 threads 8m x 4n ----------------
#define SM3_TOTAL (4096 + 2 * NK * XSTR * 2)

__global__ void __launch_bounds__(1024) k_scores() {
    int n = blockIdx.x, r = blockIdx.y, b = blockIdx.z;
    extern __shared__ char sm3[];
    int2* kmeta = (int2*)sm3;   // .x = (khash<<16)|kidx, .y = packed chunk per round
    __nv_bfloat16* xh = (__nv_bfloat16*)(sm3 + 4096);
    __nv_bfloat16* xl = (__nv_bfloat16*)(sm3 + 4096 + NK * XSTR * 2);
    int tid = threadIdx.x;
    int prevbase = ((n + NB2 - 1) & (NB2 - 1)) * CH;

    for (int j = tid; j < NK; j += 1024) {
        int keypos = (j < CH) ? (prevbase + j) : (n * CH + j - CH);
        int ki = g_hidx[b][r][keypos];
        int kh = g_hash[b][r][ki];
        int pc = 0;
#pragma unroll
        for (int rr = 0; rr < RN; rr++)
            pc |= ((g_oidx[b][rr][ki] >> 7) & 15) << (8 * rr);
        kmeta[j] = make_int2((kh << 16) | ki, pc);
    }
    __syncthreads();

    for (int t = tid; t < NK * 16; t += 1024) {
        int row = t >> 4, cg = t & 15;
        int ki = kmeta[row].x & 0xFFFF;
        float4 v = *(const float4*)&g_qn[b][ki][cg * 4];
        uint2 p0 = split2(make_float2(v.x, v.y));
        uint2 p1 = split2(make_float2(v.z, v.w));
        *(uint2*)&xh[row * XSTR + cg * 4] = make_uint2(p0.x, p1.x);
        *(uint2*)&xl[row * XSTR + cg * 4] = make_uint2(p0.y, p1.y);
    }
    __syncthreads();

    int wid = tid >> 5, lane = tid & 31;
    int wm = wid >> 2, wn = wid & 3;        // 8 m-tiles x 4 n-tiles
    int i0 = wm * 16, j0 = wn * 64;
    int g = lane >> 2, t4 = lane & 3;

    float acc[8][4];
#pragma unroll
    for (int nt = 0; nt < 8; nt++)
#pragma unroll
        for (int c = 0; c < 4; c++) acc[nt][c] = 0.f;

    const __nv_bfloat16* Ah = xh + (CH + i0) * XSTR;
    const __nv_bfloat16* Al = xl + (CH + i0) * XSTR;
#pragma unroll
    for (int ks = 0; ks < 4; ks++) {
        int k0 = ks * 16 + 2 * t4;
        uint32_t ah[4], al[4];
        ah[0] = *(const uint32_t*)&Ah[g * XSTR + k0];
        ah[1] = *(const uint32_t*)&Ah[(g + 8) * XSTR + k0];
        ah[2] = *(const uint32_t*)&Ah[g * XSTR + k0 + 8];
        ah[3] = *(const uint32_t*)&Ah[(g + 8) * XSTR + k0 + 8];
        al[0] = *(const uint32_t*)&Al[g * XSTR + k0];
        al[1] = *(const uint32_t*)&Al[(g + 8) * XSTR + k0];
        al[2] = *(const uint32_t*)&Al[g * XSTR + k0 + 8];
        al[3] = *(const uint32_t*)&Al[(g + 8) * XSTR + k0 + 8];
#pragma unroll
        for (int nt = 0; nt < 8; nt++) {
            int rowb = (j0 + nt * 8 + g) * XSTR + k0;
            uint32_t bh0 = *(const uint32_t*)&xh[rowb];
            uint32_t bh1 = *(const uint32_t*)&xh[rowb + 8];
            uint32_t bl0 = *(const uint32_t*)&xl[rowb];
            uint32_t bl1 = *(const uint32_t*)&xl[rowb + 8];
            mma_bf16(acc[nt], ah, bh0, bh1);
            mma_bf16(acc[nt], ah, bl0, bl1);
            mma_bf16(acc[nt], al, bh0, bh1);
        }
    }

    int ia = i0 + g, ib = i0 + g + 8;
    int2 qa = kmeta[CH + ia], qb = kmeta[CH + ib];
    int qidxa = qa.x & 0xFFFF, qha = qa.x >> 16, npa = qa.y;
    int qidxb = qb.x & 0xFFFF, qhb = qb.x >> 16, npb = qb.y;
    int ppa = ((npa | 0x10101010) - 0x01010101) & 0x0f0f0f0f;
    int ppb = ((npb | 0x10101010) - 0x01010101) & 0x0f0f0f0f;
    float* rowa = &g_sc[b][r][n * CH + ia][0];
    float* rowb = &g_sc[b][r][n * CH + ib][0];
#pragma unroll
    for (int nt = 0; nt < 8; nt++) {
        int j = j0 + nt * 8 + 2 * t4;          // even -> int4 aligned
        int4 km = *(const int4*)&kmeta[j];
        int kj0 = km.x & 0xFFFF, kh0 = km.x >> 16, kc0 = km.y;
        int kj1 = km.z & 0xFFFF, kh1 = km.z >> 16, kc1 = km.w;
        float o00 = acc[nt][0] * 0.125f, o01 = acc[nt][1] * 0.125f;
        float o10 = acc[nt][2] * 0.125f, o11 = acc[nt][3] * 0.125f;
        if (qidxa == kj0)                      o00 = -100000.0f;
        else if (qidxa < kj0 || qha != kh0)    o00 = -1000000000.0f;
        if (qidxa == kj1)                      o01 = -100000.0f;
        else if (qidxa < kj1 || qha != kh1)    o01 = -1000000000.0f;
        if (qidxb == kj0)                      o10 = -100000.0f;
        else if (qidxb < kj0 || qhb != kh0)    o10 = -1000000000.0f;
        if (qidxb == kj1)                      o11 = -100000.0f;
        else if (qidxb < kj1 || qhb != kh1)    o11 = -1000000000.0f;
        unsigned m;
        m = __vcmpeq4((unsigned)kc0, (unsigned)npa) | __vcmpeq4((unsigned)kc0, (unsigned)ppa);
        o00 -= c_log4[(__popc(m) >> 3) - 1];
        m = __vcmpeq4((unsigned)kc1, (unsigned)npa) | __vcmpeq4((unsigned)kc1, (unsigned)ppa);
        o01 -= c_log4[(__popc(m) >> 3) - 1];
        m = __vcmpeq4((unsigned)kc0, (unsigned)npb) | __vcmpeq4((unsigned)kc0, (unsigned)ppb);
        o10 -= c_log4[(__popc(m) >> 3) - 1];
        m = __vcmpeq4((unsigned)kc1, (unsigned)npb) | __vcmpeq4((unsigned)kc1, (unsigned)ppb);
        o11 -= c_log4[(__popc(m) >> 3) - 1];
        *(float2*)&rowa[j] = make_float2(o00, o01);
        *(float2*)&rowb[j] = make_float2(o10, o11);
    }
}

// ---------------- K4: joint softmax -> packed bf16-split p (g_pb) ----------------
__global__ void __launch_bounds__(512) k_softmax() {
    int b = blockIdx.y;
    int warp = threadIdx.x >> 5, lane = threadIdx.x & 31;
#pragma unroll 1
    for (int it = 0; it < 16; it++) {
        int l = blockIdx.x * 256 + it * 16 + warp;
        int srs[RN];
        float4 adj[RN][2];
        float mx = -3.4e38f;
#pragma unroll
        for (int r = 0; r < RN; r++) {
            srs[r] = g_oidx[b][r][l];
            const float4* srow = (const float4*)&g_sc[b][r][srs[r]][0];
            adj[r][0] = srow[lane];
            adj[r][1] = srow[lane + 32];
#pragma unroll
            for (int h = 0; h < 2; h++) {
                mx = fmaxf(mx, fmaxf(fmaxf(adj[r][h].x, adj[r][h].y),
                                     fmaxf(adj[r][h].z, adj[r][h].w)));
            }
        }
#pragma unroll
        for (int o = 16; o; o >>= 1) mx = fmaxf(mx, __shfl_xor_sync(0xffffffffu, mx, o));
        float sum = 0.f;
#pragma unroll
        for (int r = 0; r < RN; r++)
#pragma unroll
            for (int h = 0; h < 2; h++) {
                adj[r][h].x = fexp(adj[r][h].x - mx);
                adj[r][h].y = fexp(adj[r][h].y - mx);
                adj[r][h].z = fexp(adj[r][h].z - mx);
                adj[r][h].w = fexp(adj[r][h].w - mx);
                sum += adj[r][h].x + adj[r][h].y + adj[r][h].z + adj[r][h].w;
            }
#pragma unroll
        for (int o = 16; o; o >>= 1) sum += __shfl_xor_sync(0xffffffffu, sum, o);
        float inv = 1.0f / sum;
#pragma unroll
        for (int r = 0; r < RN; r++) {
            uint32_t* prow = &g_pb[b][r][srs[r]][0];
#pragma unroll
            for (int h = 0; h < 2; h++) {
                float4 w = adj[r][h];
                w.x *= inv; w.y *= inv; w.z *= inv; w.w *= inv;
                uint2 s0 = split2(make_float2(w.x, w.y));
                uint2 s1 = split2(make_float2(w.z, w.w));
                *(uint4*)&prow[h * 128 + 4 * lane] = make_uint4(s0.x, s0.y, s1.x, s1.y);
            }
        }
    }
}

// ---------------- K5: mma.sync p @ v_sorted, p fragments pre-split in g_pb ----------------
#define SM5_TOTAL (2 * 64 * VSTR * 2)

__global__ void __launch_bounds__(512) k_av(const float* __restrict__ v) {
    int n = blockIdx.x, r = blockIdx.y, b = blockIdx.z;
    extern __shared__ char sm5[];
    __nv_bfloat16* vh = (__nv_bfloat16*)sm5;
    __nv_bfloat16* vl = vh + 64 * VSTR;
    int tid = threadIdx.x;
    int prevbase = ((n + NB2 - 1) & (NB2 - 1)) * CH;

    for (int idx = tid; idx < 128 * 16; idx += 512) {
        int jp = idx & 127, f = idx >> 7;
        int ja = 2 * jp, jb = 2 * jp + 1;
        int kpa = (ja < CH) ? (prevbase + ja) : (n * CH + ja - CH);
        int kpb = (jb < CH) ? (prevbase + jb) : (n * CH + jb - CH);
        int kia = g_hidx[b][r][kpa];
        int kib = g_hidx[b][r][kpb];
        float4 va = *(const float4*)&v[((size_t)b * LEN + kia) * DIM + f * 4];
        float4 vb = *(const float4*)&v[((size_t)b * LEN + kib) * DIM + f * 4];
        float pa[4] = {va.x, va.y, va.z, va.w};
        float pb[4] = {vb.x, vb.y, vb.z, vb.w};
#pragma unroll
        for (int c = 0; c < 4; c++) {
            uint2 s = split2(make_float2(pa[c], pb[c]));
            *(uint32_t*)&vh[(f * 4 + c) * VSTR + 2 * jp] = s.x;
            *(uint32_t*)&vl[(f * 4 + c) * VSTR + 2 * jp] = s.y;
        }
    }
    __syncthreads();

    int wid = tid >> 5, lane = tid & 31;
    int wm = wid >> 1, wn = wid & 1;
    int i0 = wm * 16, d0 = wn * 32;
    int g = lane >> 2, t4 = lane & 3;

    float acc[4][4];
#pragma unroll
    for (int nt = 0; nt < 4; nt++)
#pragma unroll
        for (int c = 0; c < 4; c++) acc[nt][c] = 0.f;

    const uint32_t* pb0 = &g_pb[b][r][n * CH + i0 + g][0];
    const uint32_t* pb8 = &g_pb[b][r][n * CH + i0 + g + 8][0];
#pragma unroll 4
    for (int ks = 0; ks < 16; ks++) {
        int pi = 2 * (ks * 8 + t4);
        uint2 u0 = *(const uint2*)&pb0[pi];
        uint2 u1 = *(const uint2*)&pb8[pi];
        uint2 u2 = *(const uint2*)&pb0[pi + 8];
        uint2 u3 = *(const uint2*)&pb8[pi + 8];
        uint32_t ah[4] = {u0.x, u1.x, u2.x, u3.x};
        uint32_t al[4] = {u0.y, u1.y, u2.y, u3.y};
#pragma unroll
        for (int nt = 0; nt < 4; nt++) {
            int rowb = (d0 + nt * 8 + g) * VSTR + ks * 16;
            uint32_t bh0 = *(const uint32_t*)&vh[rowb + 2 * t4];
            uint32_t bh1 = *(const uint32_t*)&vh[rowb + 2 * t4 + 8];
            uint32_t bl0 = *(const uint32_t*)&vl[rowb + 2 * t4];
            uint32_t bl1 = *(const uint32_t*)&vl[rowb + 2 * t4 + 8];
            mma_bf16(acc[nt], ah, bh0, bh1);
            mma_bf16(acc[nt], ah, bl0, bl1);
            mma_bf16(acc[nt], al, bh0, bh1);
        }
    }

    int ia = i0 + g, ib = ia + 8;
#pragma unroll
    for (int nt = 0; nt < 4; nt++) {
        int d = d0 + nt * 8 + 2 * t4;
        *(float2*)&g_attn[b][r][n * CH + ia][d] = make_float2(acc[nt][0], acc[nt][1]);
        *(float2*)&g_attn[b][r][n * CH + ib][d] = make_float2(acc[nt][2], acc[nt][3]);
    }
}

// ---------------- K6: gather rounds back to original order, sum ----------------
__global__ void __launch_bounds__(256) k_out(float* __restrict__ out) {
    int gid = blockIdx.x * 256 + threadIdx.x;
    int dq = gid & 15;
    int l = (gid >> 4) & (LEN - 1);
    int b = gid >> 15;
    float4 s = make_float4(0.f, 0.f, 0.f, 0.f);
#pragma unroll
    for (int r = 0; r < RN; r++) {
        int sIdx = g_oidx[b][r][l];
        float4 a = *(const float4*)&g_attn[b][r][sIdx][dq * 4];
        s.x += a.x; s.y += a.y; s.z += a.z; s.w += a.w;
    }
    *(float4*)&out[((size_t)b * LEN + l) * DIM + dq * 4] = s;
}

// ---------------- launch ----------------
extern "C" void kernel_launch(void* const* d_in, const int* in_sizes, int n_in,
                              void* d_out, int out_size) {
    const float* q  = (const float*)d_in[0];
    const float* v  = (const float*)d_in[1];
    const float* rm = (const float*)d_in[2];
    float* out = (float*)d_out;

    cudaFuncSetAttribute(k_scores, cudaFuncAttributeMaxDynamicSharedMemorySize, SM3_TOTAL);
    cudaFuncSetAttribute(k_av,     cudaFuncAttributeMaxDynamicSharedMemorySize, SM5_TOTAL);

    k_rmn<<<BHN, 64>>>(rm);
    k_hash<<<dim3(LEN / 128, BHN), 128>>>(q);
    k_sort<<<BHN * RN, 256>>>();
    k_scores<<<dim3(NB2, RN, BHN), 1024, SM3_TOTAL>>>();   // launch #3 -> ncu slot
    k_softmax<<<dim3(LEN / 256, BHN), 512>>>();
    k_av<<<dim3(NB2, RN, BHN), 512, SM5_TOTAL>>>(v);
    k_out<<<(BHN * LEN * 16) / 256, 256>>>(out);
}